// round 4
// baseline (speedup 1.0000x reference)
#include <cuda_runtime.h>
#include <math.h>

#define N_STATES          25
#define LUT_PITCH         64   // padded row pitch, multiple of 32 banks -> bank = x % 32 (<=2-way conflict for x in [0,50))
#define LUT_SIZE          (N_STATES * LUT_PITCH)

#define BLOCK_THREADS     256
#define GROUPS_PER_THREAD 4
#define TILE_GROUPS       (BLOCK_THREADS * GROUPS_PER_THREAD)  // 1024 groups = 4096 spots per block

// Scratch LUT (allocation-free rule: __device__ global).
__device__ float g_lut[LUT_SIZE];

// Build the 25x64 log-prob table in fp32 (few-ulp accurate, >>1e-3 margin).
__global__ void build_lut_kernel(const float* __restrict__ means,
                                 const float* __restrict__ phis) {
    int idx = blockIdx.x * blockDim.x + threadIdx.x;
    if (idx >= LUT_SIZE) return;
    int s = idx / LUT_PITCH;
    int x = idx % LUT_PITCH;
    float v;
    if (s == 0) {
        v = (x > 0) ? -100000.0f : 0.0f;
    } else {
        float mu  = means[s];
        float phi = phis[s];
        float xf  = (float)x;
        float inv = 1.0f / (phi + mu);
        v = lgammaf(xf + phi) - lgammaf(phi) - lgammaf(xf + 1.0f)
          + phi * logf(phi * inv)
          + xf  * logf(mu  * inv);
    }
    g_lut[idx] = v;
}

// Main kernel: out[s][i] = LUT[s][obs[i]] for s in 0..24.
// Single-wave launch: grid = ceil(n_groups / TILE_GROUPS) <= 148*8 blocks,
// every block does a fixed tile of TILE_GROUPS contiguous groups (uniform work,
// no fractional grid-stride wave).
__global__ void __launch_bounds__(BLOCK_THREADS, 8)
emit_kernel(const int* __restrict__ obs,
            float* __restrict__ out,
            int n_groups,       // n_spots / 4
            long long n_spots) {
    __shared__ float lut[LUT_SIZE];
    for (int i = threadIdx.x; i < LUT_SIZE; i += BLOCK_THREADS)
        lut[i] = g_lut[i];
    __syncthreads();

    const int4* obs4 = (const int4*)obs;
    long long base = (long long)blockIdx.x * TILE_GROUPS + threadIdx.x;

    #pragma unroll
    for (int k = 0; k < GROUPS_PER_THREAD; k++) {
        long long g = base + (long long)k * BLOCK_THREADS;
        if (g >= n_groups) break;
        int4 o = obs4[g];
        #pragma unroll
        for (int s = 0; s < N_STATES; s++) {
            const float* row = lut + s * LUT_PITCH;
            float4 v;
            v.x = row[o.x];
            v.y = row[o.y];
            v.z = row[o.z];
            v.w = row[o.w];
            ((float4*)(out + (long long)s * n_spots))[g] = v;
        }
    }
}

// Scalar tail for n_spots not divisible by 4 (not hit for N_SPOTS=4M, safety).
__global__ void emit_tail_kernel(const int* __restrict__ obs,
                                 float* __restrict__ out,
                                 int tail_start, int n_spots_i,
                                 long long n_spots) {
    int i = tail_start + blockIdx.x * blockDim.x + threadIdx.x;
    if (i >= n_spots_i) return;
    int x = obs[i];
    #pragma unroll
    for (int s = 0; s < N_STATES; s++)
        out[(long long)s * n_spots + i] = g_lut[s * LUT_PITCH + x];
}

extern "C" void kernel_launch(void* const* d_in, const int* in_sizes, int n_in,
                              void* d_out, int out_size) {
    const float* state_means = (const float*)d_in[0];
    const float* state_phis  = (const float*)d_in[1];
    const int*   obs         = (const int*)d_in[2];
    float*       out         = (float*)d_out;

    int n_spots_i = in_sizes[2];
    long long n_spots = (long long)n_spots_i;

    build_lut_kernel<<<(LUT_SIZE + 255) / 256, 256>>>(state_means, state_phis);

    int n_groups = n_spots_i / 4;
    if (n_groups > 0) {
        int blocks = (n_groups + TILE_GROUPS - 1) / TILE_GROUPS;
        emit_kernel<<<blocks, BLOCK_THREADS>>>(obs, out, n_groups, n_spots);
    }

    int tail_start = n_groups * 4;
    int tail = n_spots_i - tail_start;
    if (tail > 0) {
        emit_tail_kernel<<<(tail + 255) / 256, 256>>>(obs, out, tail_start,
                                                      n_spots_i, n_spots);
    }
}

// round 5
// speedup vs baseline: 1.6693x; 1.6693x over previous
#include <cuda_runtime.h>
#include <math.h>

#define N_STATES      25
#define LUT_PITCH     64   // pitch multiple of 32 banks -> bank = x % 32
#define LUT_SIZE      (N_STATES * LUT_PITCH)
#define BLOCK_THREADS 256

// Scratch LUT (allocation-free rule: __device__ global).
__device__ float g_lut[LUT_SIZE];

// Build the 25x64 log-prob table in fp32 (few-ulp accurate, >>1e-3 margin).
__global__ void build_lut_kernel(const float* __restrict__ means,
                                 const float* __restrict__ phis) {
    int idx = blockIdx.x * blockDim.x + threadIdx.x;
    if (idx >= LUT_SIZE) return;
    int s = idx / LUT_PITCH;
    int x = idx % LUT_PITCH;
    float v;
    if (s == 0) {
        v = (x > 0) ? -100000.0f : 0.0f;
    } else {
        float mu  = means[s];
        float phi = phis[s];
        float xf  = (float)x;
        float inv = 1.0f / (phi + mu);
        v = lgammaf(xf + phi) - lgammaf(phi) - lgammaf(xf + 1.0f)
          + phi * logf(phi * inv)
          + xf  * logf(mu  * inv);
    }
    g_lut[idx] = v;
}

// Main kernel: out[s][i] = LUT[s][obs[i]].
// One int4 group (4 spots) per thread, no loop: maximal block oversubscription
// (~26 blocks/SM queued) so the scheduler always has warps with issuable stores
// while others wait on the obs load / store drain.
__global__ void __launch_bounds__(BLOCK_THREADS)
emit_kernel(const int* __restrict__ obs,
            float* __restrict__ out,
            int n_groups,        // n_spots / 4
            long long n_spots) {
    __shared__ float lut[LUT_SIZE];
    #pragma unroll
    for (int i = threadIdx.x; i < LUT_SIZE; i += BLOCK_THREADS)
        lut[i] = g_lut[i];
    __syncthreads();

    int g = blockIdx.x * BLOCK_THREADS + threadIdx.x;
    if (g >= n_groups) return;

    int4 o = ((const int4*)obs)[g];

    #pragma unroll
    for (int s = 0; s < N_STATES; s++) {
        const float* row = lut + s * LUT_PITCH;
        float4 v;
        v.x = row[o.x];
        v.y = row[o.y];
        v.z = row[o.z];
        v.w = row[o.w];
        ((float4*)(out + (long long)s * n_spots))[g] = v;
    }
}

// Scalar tail for n_spots not divisible by 4 (not hit for N_SPOTS=4M, safety).
__global__ void emit_tail_kernel(const int* __restrict__ obs,
                                 float* __restrict__ out,
                                 int tail_start, int n_spots_i,
                                 long long n_spots) {
    int i = tail_start + blockIdx.x * blockDim.x + threadIdx.x;
    if (i >= n_spots_i) return;
    int x = obs[i];
    #pragma unroll
    for (int s = 0; s < N_STATES; s++)
        out[(long long)s * n_spots + i] = g_lut[s * LUT_PITCH + x];
}

extern "C" void kernel_launch(void* const* d_in, const int* in_sizes, int n_in,
                              void* d_out, int out_size) {
    const float* state_means = (const float*)d_in[0];
    const float* state_phis  = (const float*)d_in[1];
    const int*   obs         = (const int*)d_in[2];
    float*       out         = (float*)d_out;

    int n_spots_i = in_sizes[2];
    long long n_spots = (long long)n_spots_i;

    build_lut_kernel<<<(LUT_SIZE + 255) / 256, 256>>>(state_means, state_phis);

    int n_groups = n_spots_i / 4;
    if (n_groups > 0) {
        int blocks = (n_groups + BLOCK_THREADS - 1) / BLOCK_THREADS;
        emit_kernel<<<blocks, BLOCK_THREADS>>>(obs, out, n_groups, n_spots);
    }

    int tail_start = n_groups * 4;
    int tail = n_spots_i - tail_start;
    if (tail > 0) {
        emit_tail_kernel<<<(tail + 255) / 256, 256>>>(obs, out, tail_start,
                                                      n_spots_i, n_spots);
    }
}